// round 6
// baseline (speedup 1.0000x reference)
#include <cuda_runtime.h>
#include <cstdint>

// out[r] = dot(W1[i1[r]], W2[i2[r]]) + b1[i1[r]] + b2[i2[r]]
// Row gathers via cp.async.bulk (TMA/bulk path, 512B per op) into SMEM to
// escape the per-SM L1tex outstanding-miss limit that pins LDG variants
// at ~2.1 TB/s. 32 rows/block, 64 bulk copies/block, one mbarrier phase.

#define BATCH 16384
#define EMBED 128
#define ROW_BYTES 512
#define RPB 32            // rows per block
#define THREADS 256

__device__ __forceinline__ uint32_t smem_u32(const void* p) {
    uint32_t a;
    asm("{ .reg .u64 t; cvta.to.shared.u64 t, %1; cvt.u32.u64 %0, t; }"
        : "=r"(a) : "l"(p));
    return a;
}

__device__ __forceinline__ void mbar_wait(uint32_t addr, uint32_t parity) {
    asm volatile(
        "{\n\t"
        ".reg .pred P;\n"
        "W_%=:\n\t"
        "mbarrier.try_wait.parity.acquire.cta.shared::cta.b64 P, [%0], %1, 0x989680;\n\t"
        "@!P bra W_%=;\n\t"
        "}"
        :: "r"(addr), "r"(parity) : "memory");
}

__global__ __launch_bounds__(THREADS)
void fused_embed_dot_kernel(const int* __restrict__ i1,
                            const int* __restrict__ i2,
                            const float* __restrict__ W1,
                            const float* __restrict__ W2,
                            const float* __restrict__ b1,
                            const float* __restrict__ b2,
                            float* __restrict__ out) {
    __shared__ __align__(128) float sW1[RPB][EMBED];
    __shared__ __align__(128) float sW2[RPB][EMBED];
    __shared__ float sB[2][RPB];
    __shared__ __align__(8) unsigned long long mbar;

    int tid  = threadIdx.x;
    int base = blockIdx.x * RPB;
    uint32_t mba = smem_u32(&mbar);

    if (tid == 0) {
        asm volatile("mbarrier.init.shared.b64 [%0], 1;" :: "r"(mba));
        asm volatile("fence.proxy.async.shared::cta;" ::: "memory");
    }
    __syncthreads();

    if (tid == 0) {
        asm volatile("mbarrier.arrive.expect_tx.shared.b64 _, [%0], %1;"
                     :: "r"(mba), "r"(2 * RPB * ROW_BYTES) : "memory");
    }

    // Threads 0..63 each issue one 512B bulk copy (row of W1 or W2) and
    // prefetch the matching bias into SMEM.
    if (tid < 2 * RPB) {
        int  r      = tid & (RPB - 1);
        int  second = tid >= RPB;
        int  idx    = second ? __ldg(&i2[base + r]) : __ldg(&i1[base + r]);
        const float* src = (second ? W2 : W1) + (size_t)idx * EMBED;
        uint32_t dst = smem_u32(second ? &sW2[r][0] : &sW1[r][0]);
        asm volatile(
            "cp.async.bulk.shared::cta.global.mbarrier::complete_tx::bytes "
            "[%0], [%1], %2, [%3];"
            :: "r"(dst), "l"(src), "r"(ROW_BYTES), "r"(mba) : "memory");
        sB[second][r] = __ldg(second ? &b2[idx] : &b1[idx]);
    }

    // Wait for all 32KB to land, then order sB stores for all consumers.
    mbar_wait(mba, 0);
    __syncthreads();

    // Compute: 8 lanes per row, 4 rows per warp, 8 warps -> 32 rows.
    int warp = tid >> 5;
    int lane = tid & 31;
    int r    = warp * 4 + (lane >> 3);
    int sub  = lane & 7;

    const float4* a4 = reinterpret_cast<const float4*>(&sW1[r][0]);
    const float4* c4 = reinterpret_cast<const float4*>(&sW2[r][0]);

    float4 a0 = a4[sub];      float4 c0 = c4[sub];
    float4 a1 = a4[sub + 8];  float4 c1 = c4[sub + 8];
    float4 a2 = a4[sub + 16]; float4 c2 = c4[sub + 16];
    float4 a3 = a4[sub + 24]; float4 c3 = c4[sub + 24];

    float acc0 = a0.x * c0.x;
    float acc1 = a1.x * c1.x;
    acc0 = fmaf(a0.y, c0.y, acc0);  acc1 = fmaf(a1.y, c1.y, acc1);
    acc0 = fmaf(a0.z, c0.z, acc0);  acc1 = fmaf(a1.z, c1.z, acc1);
    acc0 = fmaf(a0.w, c0.w, acc0);  acc1 = fmaf(a1.w, c1.w, acc1);
    acc0 = fmaf(a2.x, c2.x, acc0);  acc1 = fmaf(a3.x, c3.x, acc1);
    acc0 = fmaf(a2.y, c2.y, acc0);  acc1 = fmaf(a3.y, c3.y, acc1);
    acc0 = fmaf(a2.z, c2.z, acc0);  acc1 = fmaf(a3.z, c3.z, acc1);
    acc0 = fmaf(a2.w, c2.w, acc0);  acc1 = fmaf(a3.w, c3.w, acc1);
    float acc = acc0 + acc1;

    acc += __shfl_xor_sync(0xFFFFFFFFu, acc, 1);
    acc += __shfl_xor_sync(0xFFFFFFFFu, acc, 2);
    acc += __shfl_xor_sync(0xFFFFFFFFu, acc, 4);

    if (sub == 0)
        out[base + r] = acc + sB[0][r] + sB[1][r];
}

extern "C" void kernel_launch(void* const* d_in, const int* in_sizes, int n_in,
                              void* d_out, int out_size) {
    const int*   i1 = (const int*)d_in[0];
    const int*   i2 = (const int*)d_in[1];
    const float* W1 = (const float*)d_in[2];
    const float* W2 = (const float*)d_in[3];
    const float* b1 = (const float*)d_in[4];
    const float* b2 = (const float*)d_in[5];
    float* out = (float*)d_out;

    fused_embed_dot_kernel<<<BATCH / RPB, THREADS>>>(i1, i2, W1, W2, b1, b2, out);
}

// round 7
// speedup vs baseline: 1.2511x; 1.2511x over previous
#include <cuda_runtime.h>
#include <cstdint>

// out[r] = dot(W1[i1[r]], W2[i2[r]]) + b1[i1[r]] + b2[i2[r]]
// Dual-path gather: per block of 16 rows, 8 rows go through the bulk-async
// (TMA) engine into SMEM while 8 rows are fetched via LDG.128 and computed
// immediately. Tests whether the LDG and bulk engines have independent
// outstanding-request budgets (each path alone saturates at ~2.1 TB/s).

#define BATCH 16384
#define EMBED 128
#define ROW_BYTES 512
#define RPB 16          // rows per block: 8 LDG + 8 TMA
#define THREADS 256     // 8 warps

__device__ __forceinline__ uint32_t smem_u32(const void* p) {
    uint32_t a;
    asm("{ .reg .u64 t; cvta.to.shared.u64 t, %1; cvt.u32.u64 %0, t; }"
        : "=r"(a) : "l"(p));
    return a;
}

__device__ __forceinline__ void mbar_wait(uint32_t addr, uint32_t parity) {
    asm volatile(
        "{\n\t"
        ".reg .pred P;\n"
        "W_%=:\n\t"
        "mbarrier.try_wait.parity.acquire.cta.shared::cta.b64 P, [%0], %1, 0x989680;\n\t"
        "@!P bra W_%=;\n\t"
        "}"
        :: "r"(addr), "r"(parity) : "memory");
}

__global__ __launch_bounds__(THREADS)
void fused_embed_dot_kernel(const int* __restrict__ i1,
                            const int* __restrict__ i2,
                            const float* __restrict__ W1,
                            const float* __restrict__ W2,
                            const float* __restrict__ b1,
                            const float* __restrict__ b2,
                            float* __restrict__ out) {
    __shared__ __align__(128) float sW1[8][EMBED];   // TMA-landed rows
    __shared__ __align__(128) float sW2[8][EMBED];
    __shared__ __align__(8) unsigned long long mbar;

    int tid  = threadIdx.x;
    int warp = tid >> 5;
    int lane = tid & 31;
    int base = blockIdx.x * RPB;
    uint32_t mba = smem_u32(&mbar);

    if (tid == 0) {
        asm volatile("mbarrier.init.shared.b64 [%0], 1;" :: "r"(mba));
        asm volatile("fence.proxy.async.shared::cta;" ::: "memory");
    }
    __syncthreads();

    if (tid == 0) {
        asm volatile("mbarrier.arrive.expect_tx.shared.b64 _, [%0], %1;"
                     :: "r"(mba), "r"(2 * 8 * ROW_BYTES) : "memory");
    }

    // Warp 0, lanes 0..15: launch 16 bulk copies (8 rows x 2 tables) for
    // rows base+8 .. base+15.
    if (tid < 16) {
        int r      = tid & 7;
        int second = tid >> 3;
        int idx    = second ? __ldg(&i2[base + 8 + r]) : __ldg(&i1[base + 8 + r]);
        const float* src = (second ? W2 : W1) + (size_t)idx * EMBED;
        uint32_t dst = smem_u32(second ? &sW2[r][0] : &sW1[r][0]);
        asm volatile(
            "cp.async.bulk.shared::cta.global.mbarrier::complete_tx::bytes "
            "[%0], [%1], %2, [%3];"
            :: "r"(dst), "l"(src), "r"(ROW_BYTES), "r"(mba) : "memory");
    }

    // ---- LDG half: warp w computes row base+w while TMA is in flight ----
    {
        int row  = base + warp;
        int idx1 = __ldg(&i1[row]);
        int idx2 = __ldg(&i2[row]);
        float bv1 = __ldg(&b1[idx1]);
        float bv2 = __ldg(&b2[idx2]);

        const float4* r1 = reinterpret_cast<const float4*>(W1 + (size_t)idx1 * EMBED);
        const float4* r2 = reinterpret_cast<const float4*>(W2 + (size_t)idx2 * EMBED);
        float4 a = __ldg(&r1[lane]);
        float4 c = __ldg(&r2[lane]);

        float acc = a.x * c.x;
        acc = fmaf(a.y, c.y, acc);
        acc = fmaf(a.z, c.z, acc);
        acc = fmaf(a.w, c.w, acc);

        #pragma unroll
        for (int off = 16; off > 0; off >>= 1)
            acc += __shfl_xor_sync(0xFFFFFFFFu, acc, off);

        if (lane == 0)
            out[row] = acc + bv1 + bv2;
    }

    // ---- TMA half: warp w computes row base+8+w from SMEM ----
    {
        int row  = base + 8 + warp;
        int idx1 = __ldg(&i1[row]);   // L1/L2 hit (loaded above by warp 0)
        int idx2 = __ldg(&i2[row]);
        float bv1 = __ldg(&b1[idx1]); // issued before the mbarrier wait
        float bv2 = __ldg(&b2[idx2]);

        mbar_wait(mba, 0);

        const float4* a4 = reinterpret_cast<const float4*>(&sW1[warp][0]);
        const float4* c4 = reinterpret_cast<const float4*>(&sW2[warp][0]);
        float4 a = a4[lane];
        float4 c = c4[lane];

        float acc = a.x * c.x;
        acc = fmaf(a.y, c.y, acc);
        acc = fmaf(a.z, c.z, acc);
        acc = fmaf(a.w, c.w, acc);

        #pragma unroll
        for (int off = 16; off > 0; off >>= 1)
            acc += __shfl_xor_sync(0xFFFFFFFFu, acc, off);

        if (lane == 0)
            out[row] = acc + bv1 + bv2;
    }
}

extern "C" void kernel_launch(void* const* d_in, const int* in_sizes, int n_in,
                              void* d_out, int out_size) {
    const int*   i1 = (const int*)d_in[0];
    const int*   i2 = (const int*)d_in[1];
    const float* W1 = (const float*)d_in[2];
    const float* W2 = (const float*)d_in[3];
    const float* b1 = (const float*)d_in[4];
    const float* b2 = (const float*)d_in[5];
    float* out = (float*)d_out;

    // 16384 / 16 rows-per-block = 1024 blocks, 8192 warps = single wave.
    fused_embed_dot_kernel<<<BATCH / RPB, THREADS>>>(i1, i2, W1, W2, b1, b2, out);
}

// round 8
// speedup vs baseline: 1.3478x; 1.0773x over previous
#include <cuda_runtime.h>

// out[r] = dot(W1[i1[r]], W2[i2[r]]) + b1[i1[r]] + b2[i2[r]]
// R1 shape (best so far): one warp per row, lane l loads float4 l of each row.
// New: .L2::256B prefetch-size on row loads (halves independent DRAM/LTS
// transactions per 512B row; every prefetched byte is needed), biases hoisted
// to overlap the row-gather latency, no bounds guard.

#define BATCH 16384
#define EMBED 128  // 32 float4 per row

__device__ __forceinline__ float4 ldg_p256(const float4* p) {
    float4 v;
    asm volatile("ld.global.nc.L2::256B.v4.f32 {%0,%1,%2,%3}, [%4];"
                 : "=f"(v.x), "=f"(v.y), "=f"(v.z), "=f"(v.w) : "l"(p));
    return v;
}

__global__ __launch_bounds__(256)
void fused_embed_dot_kernel(const int* __restrict__ i1,
                            const int* __restrict__ i2,
                            const float* __restrict__ W1,
                            const float* __restrict__ W2,
                            const float* __restrict__ b1,
                            const float* __restrict__ b2,
                            float* __restrict__ out) {
    int warp_global = (blockIdx.x * blockDim.x + threadIdx.x) >> 5;
    int lane = threadIdx.x & 31;

    int idx1 = __ldg(&i1[warp_global]);
    int idx2 = __ldg(&i2[warp_global]);

    // Bias gathers issued early (independent 4B loads) — overlap with the
    // 512B row gathers instead of adding a serial L2 round trip at the end.
    float bv1 = __ldg(&b1[idx1]);
    float bv2 = __ldg(&b2[idx2]);

    const float4* r1 = reinterpret_cast<const float4*>(W1 + (size_t)idx1 * EMBED);
    const float4* r2 = reinterpret_cast<const float4*>(W2 + (size_t)idx2 * EMBED);

    // Two independent LDG.128 per lane with 256B prefetch granularity.
    float4 a = ldg_p256(&r1[lane]);
    float4 b = ldg_p256(&r2[lane]);

    float acc = a.x * b.x;
    acc = fmaf(a.y, b.y, acc);
    acc = fmaf(a.z, b.z, acc);
    acc = fmaf(a.w, b.w, acc);

    // Warp butterfly reduction.
    #pragma unroll
    for (int off = 16; off > 0; off >>= 1)
        acc += __shfl_xor_sync(0xFFFFFFFFu, acc, off);

    if (lane == 0)
        out[warp_global] = acc + bv1 + bv2;
}

extern "C" void kernel_launch(void* const* d_in, const int* in_sizes, int n_in,
                              void* d_out, int out_size) {
    const int*   i1 = (const int*)d_in[0];
    const int*   i2 = (const int*)d_in[1];
    const float* W1 = (const float*)d_in[2];
    const float* W2 = (const float*)d_in[3];
    const float* b1 = (const float*)d_in[4];
    const float* b2 = (const float*)d_in[5];
    float* out = (float*)d_out;

    // 16384 rows * 32 threads / 256 = 2048 blocks (R1 grid, best measured).
    fused_embed_dot_kernel<<<(BATCH * 32) / 256, 256>>>(i1, i2, W1, W2, b1, b2, out);
}